// round 1
// baseline (speedup 1.0000x reference)
#include <cuda_runtime.h>
#include <cstdint>

// Problem constants (shape-specialized; T and S re-derived from sizes at launch)
#define B_SZ   1024
#define I_SZ   64
#define U_SZ   1024
#define NG     4096        // 4*U, gate order i,f,g,o
#define KC     64          // K-chunk
#define NCH    17          // (I + U)/KC = 1088/64
#define BM     128
#define UN     64          // units per CTA
// CTA computes z tile [BM x 256] where col = 4*unit_local + gate (interleaved)

#define AS_STRIDE 68       // 64 + 4 pad  -> conflict-free A frag LDS
#define WS_STRIDE 260      // 256 + 4 pad
#define SMEM_FLOATS (BM*AS_STRIDE + KC*WS_STRIDE)

// Persistent device state (allowed: __device__ globals, no allocation)
__device__ float g_h[2][B_SZ * U_SZ];
__device__ float g_c[B_SZ * U_SZ];
__device__ float g_pred[B_SZ * I_SZ];

__device__ __forceinline__ float to_tf32(float x) {
    uint32_t u;
    asm("cvt.rna.tf32.f32 %0, %1;" : "=r"(u) : "f"(x));
    return __uint_as_float(u);
}

__device__ __forceinline__ void mma_tf32(float (&d)[4], const uint32_t (&a)[4],
                                         const uint32_t (&b)[2]) {
    asm volatile(
        "mma.sync.aligned.m16n8k8.row.col.f32.tf32.tf32.f32 "
        "{%0,%1,%2,%3}, {%4,%5,%6,%7}, {%8,%9}, {%0,%1,%2,%3};\n"
        : "+f"(d[0]), "+f"(d[1]), "+f"(d[2]), "+f"(d[3])
        : "r"(a[0]), "r"(a[1]), "r"(a[2]), "r"(a[3]), "r"(b[0]), "r"(b[1]));
}

__device__ __forceinline__ float sigm(float x) { return 1.0f / (1.0f + expf(-x)); }

// Zero h[0] and c at the start of every launch (deterministic state)
__global__ void init_state_kernel() {
    int i = blockIdx.x * blockDim.x + threadIdx.x;
    if (i < B_SZ * U_SZ) {
        g_h[0][i] = 0.0f;
        g_c[i] = 0.0f;
    }
}

// One LSTM step: z = [x,h] @ [Wk;Wr] + b, cell update, writes g_h[par^1] and g_c.
// x source: external pointer (warmup) or g_pred (decode).
__global__ __launch_bounds__(256, 1)
void lstm_step_kernel(const float* __restrict__ x, int xstride, int par, int use_pred,
                      const float* __restrict__ Wk, const float* __restrict__ Wr,
                      const float* __restrict__ bias) {
    extern __shared__ float sm[];
    float* as = sm;                       // [BM][AS_STRIDE]
    float* ws = sm + BM * AS_STRIDE;      // [KC][WS_STRIDE]

    const int tid  = threadIdx.x;
    const int lane = tid & 31;
    const int wid  = tid >> 5;
    const int gid  = lane >> 2;   // 0..7
    const int tig  = lane & 3;    // 0..3

    const int utile = blockIdx.x & 15;
    const int mtile = blockIdx.x >> 4;
    const int u0 = utile * UN;
    const int m0 = mtile * BM;

    // warp grid: 2 (M) x 4 (N); warp tile 64 x 64
    const int wm0 = (wid >> 2) * 64;
    const int wn0 = (wid & 3) * 64;

    const float* h_in  = g_h[par];
    float*       h_out = g_h[par ^ 1];
    const float* xp = use_pred ? g_pred : x;
    const int    xs = use_pred ? I_SZ : xstride;

    float acc[4][8][4];
#pragma unroll
    for (int mt = 0; mt < 4; mt++)
#pragma unroll
        for (int nt = 0; nt < 8; nt++)
#pragma unroll
            for (int q = 0; q < 4; q++) acc[mt][nt][q] = 0.0f;

    for (int kc = 0; kc < NCH; kc++) {
        // ---- load A chunk [BM x 64] (fp32 -> tf32) ----
        if (kc == 0) {
#pragma unroll 4
            for (int i = tid; i < BM * 16; i += 256) {
                int r = i >> 4, c4 = (i & 15) << 2;
                float4 v = *(const float4*)(xp + (size_t)(m0 + r) * xs + c4);
                float* dst = as + r * AS_STRIDE + c4;
                dst[0] = to_tf32(v.x); dst[1] = to_tf32(v.y);
                dst[2] = to_tf32(v.z); dst[3] = to_tf32(v.w);
            }
        } else {
            const float* hsrc = h_in + (size_t)m0 * U_SZ + (size_t)(kc - 1) * KC;
#pragma unroll 4
            for (int i = tid; i < BM * 16; i += 256) {
                int r = i >> 4, c4 = (i & 15) << 2;
                float4 v = *(const float4*)(hsrc + (size_t)r * U_SZ + c4);
                float* dst = as + r * AS_STRIDE + c4;
                dst[0] = to_tf32(v.x); dst[1] = to_tf32(v.y);
                dst[2] = to_tf32(v.z); dst[3] = to_tf32(v.w);
            }
        }
        // ---- load W chunk [64 x 256], col = 4*u + g  (gate-interleaved) ----
        {
            const float* wbase = (kc == 0) ? Wk : (Wr + (size_t)(kc - 1) * KC * NG);
#pragma unroll 8
            for (int i = tid; i < KC * 256; i += 256) {
                int r = i >> 8, nl = i & 255;
                float v = __ldg(wbase + (size_t)r * NG + (nl & 3) * U_SZ + u0 + (nl >> 2));
                ws[r * WS_STRIDE + nl] = to_tf32(v);
            }
        }
        __syncthreads();

        // ---- MMA over this K chunk ----
#pragma unroll
        for (int ks = 0; ks < 8; ks++) {
            const int kb = ks * 8;
            uint32_t af[4][4];
#pragma unroll
            for (int mt = 0; mt < 4; mt++) {
                int mr = wm0 + mt * 16 + gid;
                af[mt][0] = __float_as_uint(as[mr * AS_STRIDE + kb + tig]);
                af[mt][1] = __float_as_uint(as[(mr + 8) * AS_STRIDE + kb + tig]);
                af[mt][2] = __float_as_uint(as[mr * AS_STRIDE + kb + tig + 4]);
                af[mt][3] = __float_as_uint(as[(mr + 8) * AS_STRIDE + kb + tig + 4]);
            }
#pragma unroll
            for (int nt = 0; nt < 8; nt++) {
                uint32_t bf[2];
                int nb = wn0 + nt * 8 + gid;
                bf[0] = __float_as_uint(ws[(kb + tig) * WS_STRIDE + nb]);
                bf[1] = __float_as_uint(ws[(kb + tig + 4) * WS_STRIDE + nb]);
#pragma unroll
                for (int mt = 0; mt < 4; mt++) mma_tf32(acc[mt][nt], af[mt], bf);
            }
        }
        __syncthreads();
    }

    // ---- epilogue: bias + gates + cell update ----
    // Thread's accum cols within an n-tile: (2*tig, 2*tig+1).
    // With col = 4*unit + gate: tig even -> gates (i,f); tig odd -> gates (g,o)
    // of the SAME unit as partner lane (lane^1). Exchange via shfl_xor(1).
    const int pg = tig & 1;
#pragma unroll
    for (int mt = 0; mt < 4; mt++) {
        const int r1 = m0 + wm0 + mt * 16 + gid;   // global batch row
#pragma unroll
        for (int nt = 0; nt < 8; nt++) {
            float c0 = acc[mt][nt][0], c1 = acc[mt][nt][1];
            float c2 = acc[mt][nt][2], c3 = acc[mt][nt][3];
            const int col  = wn0 + nt * 8 + 2 * tig;
            const int unit = u0 + (col >> 2);
            const float ba0 = pg ? __ldg(bias + 2 * U_SZ + unit) : __ldg(bias + unit);
            const float ba1 = pg ? __ldg(bias + 3 * U_SZ + unit) : __ldg(bias + U_SZ + unit);
            c0 += ba0; c1 += ba1; c2 += ba0; c3 += ba1;

            float s0 = __shfl_xor_sync(0xffffffffu, c0, 1);
            float s1 = __shfl_xor_sync(0xffffffffu, c1, 1);
            float s2 = __shfl_xor_sync(0xffffffffu, c2, 1);
            float s3 = __shfl_xor_sync(0xffffffffu, c3, 1);

            // row r1
            {
                float gi = pg ? s0 : c0, gf = pg ? s1 : c1;
                float gg = pg ? c0 : s0, go = pg ? c1 : s1;
                int idx = r1 * U_SZ + unit;
                float cold = g_c[idx];
                float cn = sigm(gf) * cold + sigm(gi) * tanhf(gg);
                float hv = sigm(go) * tanhf(cn);
                if (!pg) { g_c[idx] = cn; h_out[idx] = hv; }
            }
            // row r1 + 8
            {
                float gi = pg ? s2 : c2, gf = pg ? s3 : c3;
                float gg = pg ? c2 : s2, go = pg ? c3 : s3;
                int idx = (r1 + 8) * U_SZ + unit;
                float cold = g_c[idx];
                float cn = sigm(gf) * cold + sigm(gi) * tanhf(gg);
                float hv = sigm(go) * tanhf(cn);
                if (!pg) { g_c[idx] = cn; h_out[idx] = hv; }
            }
        }
    }
}

// pred = h @ Wd + bd ; writes g_pred and the gathered output columns for step s.
__global__ __launch_bounds__(256)
void dense_head_kernel(int par, const float* __restrict__ Wd, const float* __restrict__ bd,
                       const int* __restrict__ oidx, int n_idx,
                       float* __restrict__ out, int s, int S) {
    __shared__ float hs[8 * U_SZ];   // 32 KB: 8 batch rows of h
    const int tid = threadIdx.x;
    const int r0 = blockIdx.x * 8;
    const float* h = g_h[par];
    for (int i = tid; i < 8 * U_SZ; i += 256)
        hs[i] = h[(size_t)(r0 + (i >> 10)) * U_SZ + (i & 1023)];
    __syncthreads();

    const int icol = tid & 63;
    const int rr = tid >> 6;       // 0..3
#pragma unroll
    for (int rp = 0; rp < 2; rp++) {
        const int r = rr + rp * 4;
        const float* hrow = hs + r * U_SZ;
        float acc = __ldg(bd + icol);
#pragma unroll 8
        for (int u = 0; u < U_SZ; u++) acc += hrow[u] * __ldg(Wd + (size_t)u * I_SZ + icol);
        const int gb = r0 + r;
        g_pred[gb * I_SZ + icol] = acc;
        for (int j = 0; j < n_idx; j++)
            if (__ldg(oidx + j) == icol)
                out[(size_t)gb * S * n_idx + s * n_idx + j] = acc;
    }
}

extern "C" void kernel_launch(void* const* d_in, const int* in_sizes, int n_in,
                              void* d_out, int out_size) {
    const float* inputs = (const float*)d_in[0];
    const float* Wk     = (const float*)d_in[1];
    const float* Wr     = (const float*)d_in[2];
    const float* bias   = (const float*)d_in[3];
    const float* Wd     = (const float*)d_in[4];
    const float* bd     = (const float*)d_in[5];
    const int*   oidx   = (const int*)d_in[6];
    float*       out    = (float*)d_out;

    const int T     = in_sizes[0] / (B_SZ * I_SZ);   // 256
    const int n_idx = in_sizes[6];                   // 2
    const int S     = out_size / (B_SZ * n_idx);     // 64

    const size_t smem = SMEM_FLOATS * sizeof(float); // ~99 KB -> needs opt-in
    cudaFuncSetAttribute(lstm_step_kernel,
                         cudaFuncAttributeMaxDynamicSharedMemorySize, (int)smem);

    init_state_kernel<<<(B_SZ * U_SZ + 255) / 256, 256>>>();

    int par = 0;
    // warmup over the input sequence
    for (int t = 0; t < T; t++) {
        lstm_step_kernel<<<128, 256, smem>>>(inputs + (size_t)t * I_SZ, T * I_SZ,
                                             par, 0, Wk, Wr, bias);
        par ^= 1;
    }
    // first prediction
    dense_head_kernel<<<128, 256>>>(par, Wd, bd, oidx, n_idx, out, 0, S);
    // autoregressive decode
    for (int s = 1; s < S; s++) {
        lstm_step_kernel<<<128, 256, smem>>>(nullptr, 0, par, 1, Wk, Wr, bias);
        par ^= 1;
        dense_head_kernel<<<128, 256>>>(par, Wd, bd, oidx, n_idx, out, s, S);
    }
}

// round 3
// speedup vs baseline: 1.4723x; 1.4723x over previous
#include <cuda_runtime.h>
#include <cstdint>

// Shape-specialized constants
#define B_SZ   1024
#define I_SZ   64
#define U_SZ   1024
#define NG     4096        // 4*U
#define KC     64          // K-chunk
#define NCH    17          // (I + U)/KC
#define BM     128
#define UN     64          // units per CTA
#define T_SZ   256

#define A_ST   68          // 64 + 4 pad (conflict-free A LDS)
#define W_ST   264         // 256 + 8 pad (conflict-free W LDS: bank = 8*tig+gid)
#define A_BUF  (BM * A_ST)         // 8704 floats
#define W_BUF  (KC * W_ST)         // 16896 floats
#define SMEM_FLOATS (2 * A_BUF + 2 * W_BUF)   // 51200 floats = 200 KB

// Persistent device state (no allocation — __device__ globals)
__device__ float g_h[2][B_SZ * U_SZ];
__device__ float g_c[B_SZ * U_SZ];
__device__ float g_pred[B_SZ * I_SZ];
__device__ float g_x[B_SZ * T_SZ * I_SZ];          // tf32-rounded inputs
__device__ float g_Wt[NCH * KC * NG];              // gate-interleaved tf32 weights

__device__ __forceinline__ float to_tf32(float x) {
    uint32_t u;
    asm("cvt.rna.tf32.f32 %0, %1;" : "=r"(u) : "f"(x));
    return __uint_as_float(u);
}

__device__ __forceinline__ void mma_tf32(float (&d)[4], const uint32_t (&a)[4],
                                         const uint32_t (&b)[2]) {
    asm volatile(
        "mma.sync.aligned.m16n8k8.row.col.f32.tf32.tf32.f32 "
        "{%0,%1,%2,%3}, {%4,%5,%6,%7}, {%8,%9}, {%0,%1,%2,%3};\n"
        : "+f"(d[0]), "+f"(d[1]), "+f"(d[2]), "+f"(d[3])
        : "r"(a[0]), "r"(a[1]), "r"(a[2]), "r"(a[3]), "r"(b[0]), "r"(b[1]));
}

__device__ __forceinline__ void cp16(uint32_t dst_smem, const void* src) {
    asm volatile("cp.async.cg.shared.global [%0], [%1], 16;\n"
                 :: "r"(dst_smem), "l"(src));
}

__device__ __forceinline__ float sigm(float x) { return 1.0f / (1.0f + expf(-x)); }

// ---------------- prep kernels (once per launch) ----------------

__global__ void init_state_kernel() {
    int i = blockIdx.x * blockDim.x + threadIdx.x;
    if (i < B_SZ * U_SZ) { g_h[0][i] = 0.0f; g_c[i] = 0.0f; }
}

__global__ void prep_x_kernel(const float* __restrict__ x, int n) {
    int i = blockIdx.x * blockDim.x + threadIdx.x;
    if (i < n) g_x[i] = to_tf32(x[i]);
}

// g_Wt[kc][r][c], c = 4*u + g  (unit-major interleave -> each utile slice contiguous)
__global__ void prep_w_kernel(const float* __restrict__ Wk, const float* __restrict__ Wr) {
    int i = blockIdx.x * blockDim.x + threadIdx.x;
    if (i >= NCH * KC * NG) return;
    int c  = i & (NG - 1);
    int r  = (i >> 12) & (KC - 1);
    int kc = i >> 18;                        // KC*NG = 2^18
    const float* src = (kc == 0) ? (Wk + (size_t)r * NG)
                                 : (Wr + ((size_t)(kc - 1) * KC + r) * NG);
    g_Wt[i] = to_tf32(src[(c & 3) * U_SZ + (c >> 2)]);
}

// ---------------- LSTM step ----------------

__global__ __launch_bounds__(256, 1)
void lstm_step_kernel(int t, int par, int use_pred, const float* __restrict__ bias) {
    extern __shared__ float sm[];
    uint32_t smb = (uint32_t)__cvta_generic_to_shared(sm);

    const int tid  = threadIdx.x;
    const int lane = tid & 31;
    const int wid  = tid >> 5;
    const int gid  = lane >> 2;   // 0..7
    const int tig  = lane & 3;    // 0..3

    const int utile = blockIdx.x & 15;
    const int mtile = blockIdx.x >> 4;
    const int u0 = utile * UN;
    const int m0 = mtile * BM;

    const int wm0 = (wid >> 2) * 64;   // 2 warps in M
    const int wn0 = (wid & 3) * 64;    // 4 warps in N

    const float* h_in  = g_h[par];
    float*       h_out = g_h[par ^ 1];

    // issue cp.async for chunk kc into buffer kc&1
    auto issue = [&](int kc) {
        int buf = kc & 1;
        // ---- A chunk [128 x 64] ----
        const float* abase; int astr;
        if (kc == 0) {
            if (use_pred) { abase = g_pred + (size_t)m0 * I_SZ; astr = I_SZ; }
            else          { abase = g_x + ((size_t)m0 * T_SZ + t) * I_SZ; astr = T_SZ * I_SZ; }
        } else {
            abase = h_in + (size_t)m0 * U_SZ + (size_t)(kc - 1) * KC; astr = U_SZ;
        }
        uint32_t abuf = smb + (uint32_t)(buf * A_BUF) * 4u;
#pragma unroll
        for (int j = 0; j < 8; j++) {
            int idx = tid + j * 256;
            int r = idx >> 4, s4 = (idx & 15) << 2;
            cp16(abuf + (uint32_t)(r * A_ST + s4) * 4u, abase + (size_t)r * astr + s4);
        }
        // ---- W chunk [64 x 256] (pre-interleaved, contiguous slice) ----
        const float* wbase = g_Wt + (size_t)kc * KC * NG + (size_t)u0 * 4;
        uint32_t wbuf = smb + (uint32_t)(2 * A_BUF + buf * W_BUF) * 4u;
#pragma unroll
        for (int j = 0; j < 16; j++) {
            int idx = tid + j * 256;
            int r = idx >> 6, s4 = (idx & 63) << 2;
            cp16(wbuf + (uint32_t)(r * W_ST + s4) * 4u, wbase + (size_t)r * NG + s4);
        }
        asm volatile("cp.async.commit_group;\n");
    };

    float acc[4][8][4];
#pragma unroll
    for (int mt = 0; mt < 4; mt++)
#pragma unroll
        for (int nt = 0; nt < 8; nt++)
#pragma unroll
            for (int q = 0; q < 4; q++) acc[mt][nt][q] = 0.0f;

    issue(0);

    for (int kc = 0; kc < NCH; kc++) {
        if (kc + 1 < NCH) {
            issue(kc + 1);
            asm volatile("cp.async.wait_group 1;\n");
        } else {
            asm volatile("cp.async.wait_group 0;\n");
        }
        __syncthreads();

        const float* asb = sm + (kc & 1) * A_BUF;
        const float* wsb = sm + 2 * A_BUF + (kc & 1) * W_BUF;

#pragma unroll
        for (int ks = 0; ks < 8; ks++) {
            const int kb = ks * 8;
            uint32_t af[4][4];
#pragma unroll
            for (int mt = 0; mt < 4; mt++) {
                int mr = wm0 + mt * 16 + gid;
                af[mt][0] = __float_as_uint(asb[mr * A_ST + kb + tig]);
                af[mt][1] = __float_as_uint(asb[(mr + 8) * A_ST + kb + tig]);
                af[mt][2] = __float_as_uint(asb[mr * A_ST + kb + tig + 4]);
                af[mt][3] = __float_as_uint(asb[(mr + 8) * A_ST + kb + tig + 4]);
            }
#pragma unroll
            for (int nt = 0; nt < 8; nt++) {
                uint32_t bf[2];
                int nb = wn0 + nt * 8 + gid;
                bf[0] = __float_as_uint(wsb[(kb + tig) * W_ST + nb]);
                bf[1] = __float_as_uint(wsb[(kb + tig + 4) * W_ST + nb]);
#pragma unroll
                for (int mt = 0; mt < 4; mt++) mma_tf32(acc[mt][nt], af[mt], bf);
            }
        }
        __syncthreads();
    }

    // ---- epilogue: bias + gates + cell update ----
    // col = 4*unit + gate; tig even lane holds (i,f), odd lane (g,o) of same unit.
    const int pg = tig & 1;
#pragma unroll
    for (int mt = 0; mt < 4; mt++) {
        const int r1 = m0 + wm0 + mt * 16 + gid;
#pragma unroll
        for (int nt = 0; nt < 8; nt++) {
            float c0 = acc[mt][nt][0], c1 = acc[mt][nt][1];
            float c2 = acc[mt][nt][2], c3 = acc[mt][nt][3];
            const int col  = wn0 + nt * 8 + 2 * tig;
            const int unit = u0 + (col >> 2);
            const float ba0 = pg ? __ldg(bias + 2 * U_SZ + unit) : __ldg(bias + unit);
            const float ba1 = pg ? __ldg(bias + 3 * U_SZ + unit) : __ldg(bias + U_SZ + unit);
            c0 += ba0; c1 += ba1; c2 += ba0; c3 += ba1;

            float s0 = __shfl_xor_sync(0xffffffffu, c0, 1);
            float s1 = __shfl_xor_sync(0xffffffffu, c1, 1);
            float s2 = __shfl_xor_sync(0xffffffffu, c2, 1);
            float s3 = __shfl_xor_sync(0xffffffffu, c3, 1);

            {
                float gi = pg ? s0 : c0, gf = pg ? s1 : c1;
                float gg = pg ? c0 : s0, go = pg ? c1 : s1;
                int idx = r1 * U_SZ + unit;
                float cold = g_c[idx];
                float cn = sigm(gf) * cold + sigm(gi) * tanhf(gg);
                float hv = sigm(go) * tanhf(cn);
                if (!pg) { g_c[idx] = cn; h_out[idx] = to_tf32(hv); }
            }
            {
                float gi = pg ? s2 : c2, gf = pg ? s3 : c3;
                float gg = pg ? c2 : s2, go = pg ? c3 : s3;
                int idx = (r1 + 8) * U_SZ + unit;
                float cold = g_c[idx];
                float cn = sigm(gf) * cold + sigm(gi) * tanhf(gg);
                float hv = sigm(go) * tanhf(cn);
                if (!pg) { g_c[idx] = cn; h_out[idx] = to_tf32(hv); }
            }
        }
    }
}

// ---------------- dense head ----------------

__global__ __launch_bounds__(256)
void dense_head_kernel(int par, const float* __restrict__ Wd, const float* __restrict__ bd,
                       const int* __restrict__ oidx, int n_idx,
                       float* __restrict__ out, int s, int S) {
    __shared__ float hs[8 * U_SZ];
    const int tid = threadIdx.x;
    const int r0 = blockIdx.x * 8;
    const float* h = g_h[par];
    for (int i = tid; i < 8 * U_SZ; i += 256)
        hs[i] = h[(size_t)(r0 + (i >> 10)) * U_SZ + (i & 1023)];
    __syncthreads();

    const int icol = tid & 63;
    const int rr = tid >> 6;
#pragma unroll
    for (int rp = 0; rp < 2; rp++) {
        const int r = rr + rp * 4;
        const float* hrow = hs + r * U_SZ;
        float a0 = 0.f, a1 = 0.f, a2 = 0.f, a3 = 0.f;
#pragma unroll 4
        for (int u = 0; u < U_SZ; u += 4) {
            a0 += hrow[u]     * __ldg(Wd + (size_t)u * I_SZ + icol);
            a1 += hrow[u + 1] * __ldg(Wd + (size_t)(u + 1) * I_SZ + icol);
            a2 += hrow[u + 2] * __ldg(Wd + (size_t)(u + 2) * I_SZ + icol);
            a3 += hrow[u + 3] * __ldg(Wd + (size_t)(u + 3) * I_SZ + icol);
        }
        float acc = __ldg(bd + icol) + (a0 + a1) + (a2 + a3);
        const int gb = r0 + r;
        g_pred[gb * I_SZ + icol] = to_tf32(acc);   // tf32 for next-step MMA input
        for (int j = 0; j < n_idx; j++)
            if (__ldg(oidx + j) == icol)
                out[(size_t)gb * S * n_idx + s * n_idx + j] = acc;  // full precision out
    }
}

// ---------------- launch ----------------

extern "C" void kernel_launch(void* const* d_in, const int* in_sizes, int n_in,
                              void* d_out, int out_size) {
    const float* inputs = (const float*)d_in[0];
    const float* Wk     = (const float*)d_in[1];
    const float* Wr     = (const float*)d_in[2];
    const float* bias   = (const float*)d_in[3];
    const float* Wd     = (const float*)d_in[4];
    const float* bd     = (const float*)d_in[5];
    const int*   oidx   = (const int*)d_in[6];
    float*       out    = (float*)d_out;

    const int T     = in_sizes[0] / (B_SZ * I_SZ);   // 256
    const int n_idx = in_sizes[6];                   // 2
    const int S     = out_size / (B_SZ * n_idx);     // 64

    const size_t smem = SMEM_FLOATS * sizeof(float); // 200 KB
    cudaFuncSetAttribute(lstm_step_kernel,
                         cudaFuncAttributeMaxDynamicSharedMemorySize, (int)smem);

    init_state_kernel<<<(B_SZ * U_SZ + 255) / 256, 256>>>();
    prep_x_kernel<<<(B_SZ * T * I_SZ + 255) / 256, 256>>>(inputs, B_SZ * T * I_SZ);
    prep_w_kernel<<<(NCH * KC * NG + 255) / 256, 256>>>(Wk, Wr);

    int par = 0;
    for (int t = 0; t < T; t++) {
        lstm_step_kernel<<<128, 256, smem>>>(t, par, 0, bias);
        par ^= 1;
    }
    dense_head_kernel<<<128, 256>>>(par, Wd, bd, oidx, n_idx, out, 0, S);
    for (int s = 1; s < S; s++) {
        lstm_step_kernel<<<128, 256, smem>>>(0, par, 1, bias);
        par ^= 1;
        dense_head_kernel<<<128, 256>>>(par, Wd, bd, oidx, n_idx, out, s, S);
    }
}

// round 6
// speedup vs baseline: 1.6174x; 1.0986x over previous
#include <cuda_runtime.h>
#include <cstdint>

// Shapes (specialized)
#define B_SZ   1024
#define I_SZ   64
#define U_SZ   1024
#define T_SZ   256
#define KC     64          // K per chunk
#define NCHK   17          // (64+1024)/64
#define BM     128
#define BN     256         // 64 units x 4 gates (col = 4*u_local + gate)
#define UN     64

// Fragment-major chunk images:
//  A chunk:  [ks(8)][m16(8)][lane(32)][q(4)]  = 8192 floats = 32KB
//  W chunk:  [ks(8)][nbp(16)][lane(32)][jp(4)] = 16384 floats = 64KB
#define A_CH_FLOATS 8192
#define W_CH_FLOATS 16384
#define STAGE_FLOATS (A_CH_FLOATS + W_CH_FLOATS)       // 24576 = 96KB
#define SMEM_BYTES (2 * STAGE_FLOATS * 4)              // 192KB

// ---------------- device state ----------------
__device__ float g_h[2][B_SZ * U_SZ];                   // linear h (dense head)
__device__ float g_c[B_SZ * U_SZ];
__device__ float g_hFrag[2][8 * 16 * A_CH_FLOATS];      // [par][mtile][ch-1][frag]
__device__ float g_xFrag[8 * 256 * A_CH_FLOATS];        // [mtile][t][frag]
__device__ float g_pFrag[8 * A_CH_FLOATS];              // [mtile][frag]
__device__ float g_WFrag[NCHK * 16 * W_CH_FLOATS];      // [kc][utile][frag]

// ---------------- helpers ----------------
__device__ __forceinline__ float to_tf32(float x) {
    uint32_t u; asm("cvt.rna.tf32.f32 %0, %1;" : "=r"(u) : "f"(x));
    return __uint_as_float(u);
}
__device__ __forceinline__ void mma_tf32(float (&d)[4], const uint32_t (&a)[4],
                                         uint32_t b0, uint32_t b1) {
    asm volatile(
        "mma.sync.aligned.m16n8k8.row.col.f32.tf32.tf32.f32 "
        "{%0,%1,%2,%3}, {%4,%5,%6,%7}, {%8,%9}, {%0,%1,%2,%3};\n"
        : "+f"(d[0]), "+f"(d[1]), "+f"(d[2]), "+f"(d[3])
        : "r"(a[0]), "r"(a[1]), "r"(a[2]), "r"(a[3]), "r"(b0), "r"(b1));
}
__device__ __forceinline__ void cp16(uint32_t dst, const void* src) {
    asm volatile("cp.async.cg.shared.global [%0], [%1], 16;\n" :: "r"(dst), "l"(src));
}
__device__ __forceinline__ float sigm(float x) { return 1.0f / (1.0f + expf(-x)); }

// frag index for an A-side element (m_local in [0,128), k in [0,64)) within a chunk
__device__ __forceinline__ int a_frag_idx(int m_local, int k) {
    int m16 = m_local >> 4, r16 = m_local & 15;
    int rhi = r16 >> 3, gid = r16 & 7;
    int ks = k >> 3, tig = k & 3, khi = (k >> 2) & 1;
    return (((ks * 8 + m16) * 32) + (gid * 4 + tig)) * 4 + (khi * 2 + rhi);
}

// ---------------- prep kernels (once per launch) ----------------
__global__ void init_state_kernel() {
    int i = blockIdx.x * blockDim.x + threadIdx.x;
    if (i < B_SZ * U_SZ) g_c[i] = 0.0f;
    if (i < 8 * 16 * A_CH_FLOATS) g_hFrag[0][i] = 0.0f;
}

__global__ void prep_x_kernel(const float* __restrict__ x) {
    int i = blockIdx.x * blockDim.x + threadIdx.x;   // over B*T*I
    if (i >= B_SZ * T_SZ * I_SZ) return;
    int col = i & 63, t = (i >> 6) & 255, row = i >> 14;
    int mtile = row >> 7, m = row & 127;
    g_xFrag[((size_t)mtile * 256 + t) * A_CH_FLOATS + a_frag_idx(m, col)] = to_tf32(x[i]);
}

__global__ void prep_w_kernel(const float* __restrict__ Wk, const float* __restrict__ Wr) {
    int i = blockIdx.x * blockDim.x + threadIdx.x;   // over NCHK*16*W_CH_FLOATS
    if (i >= NCHK * 16 * W_CH_FLOATS) return;
    int jp    = i & 3;            // j = jp>>1 (n-tile pair member), p = jp&1 (k half)
    int lane  = (i >> 2) & 31;
    int nbp   = (i >> 7) & 15;
    int ks    = (i >> 11) & 7;
    int utile = (i >> 14) & 15;
    int kc    = i >> 18;          // 16*W_CH_FLOATS = 2^18
    int gid = lane >> 2, tig = lane & 3;
    int n_local = (nbp * 2 + (jp >> 1)) * 8 + gid;    // 0..255, = 4*u_local + gate
    int ul = n_local >> 2, gate = n_local & 3;
    int colW = gate * U_SZ + utile * UN + ul;
    int kg = kc * KC + ks * 8 + tig + 4 * (jp & 1);
    float v = (kg < I_SZ) ? Wk[(size_t)kg * 4096 + colW]
                          : Wr[(size_t)(kg - I_SZ) * 4096 + colW];
    g_WFrag[i] = to_tf32(v);
}

// ---------------- LSTM step ----------------
__global__ __launch_bounds__(256, 1)
void lstm_step_kernel(int t, int par, int use_pred, const float* __restrict__ bias) {
    extern __shared__ float sm[];
    uint32_t smb;
    asm("{ .reg .u64 t; cvta.to.shared.u64 t, %1; cvt.u32.u64 %0, t; }" : "=r"(smb) : "l"(sm));

    const int tid  = threadIdx.x;
    const int lane = tid & 31;
    const int wid  = tid >> 5;
    const int gid  = lane >> 2;
    const int tig  = lane & 3;

    const int utile = blockIdx.x & 15;
    const int mtile = blockIdx.x >> 4;
    const int u0 = utile * UN;
    const int m0 = mtile * BM;

    const int wm0 = (wid >> 2) * 64;     // 2 warps in M
    const int wn0 = (wid & 3) * 64;      // 4 warps in N
    const int m16b = (wid >> 2) * 4;     // A frag m16 base (+mt)
    const int nbpb = (wid & 3) * 4;      // W frag nbp base (+ntp)

    // issue cp.async for chunk ch into stage ch&1 (pure linear 16B copies)
    auto issue = [&](int ch) {
        uint32_t stg = smb + (uint32_t)(ch & 1) * (STAGE_FLOATS * 4u);
        const float4* a;
        if (ch == 0)
            a = use_pred ? (const float4*)(g_pFrag + (size_t)mtile * A_CH_FLOATS)
                         : (const float4*)(g_xFrag + ((size_t)mtile * 256 + t) * A_CH_FLOATS);
        else
            a = (const float4*)(g_hFrag[par] + ((size_t)mtile * 16 + (ch - 1)) * A_CH_FLOATS);
#pragma unroll
        for (int j = 0; j < 8; j++)
            cp16(stg + (uint32_t)(tid + j * 256) * 16u, a + tid + j * 256);
        const float4* b = (const float4*)(g_WFrag + ((size_t)ch * 16 + utile) * W_CH_FLOATS);
#pragma unroll
        for (int j = 0; j < 16; j++)
            cp16(stg + A_CH_FLOATS * 4u + (uint32_t)(tid + j * 256) * 16u, b + tid + j * 256);
        asm volatile("cp.async.commit_group;\n");
    };

    float acc[4][8][4];
#pragma unroll
    for (int mt = 0; mt < 4; mt++)
#pragma unroll
        for (int nt = 0; nt < 8; nt++)
#pragma unroll
            for (int q = 0; q < 4; q++) acc[mt][nt][q] = 0.0f;

    issue(0);

    for (int ch = 0; ch < NCHK; ch++) {
        if (ch + 1 < NCHK) {
            issue(ch + 1);
            asm volatile("cp.async.wait_group 1;\n" ::: "memory");
        } else {
            asm volatile("cp.async.wait_group 0;\n" ::: "memory");
        }
        __syncthreads();

        const float* as = sm + (ch & 1) * STAGE_FLOATS;
        const float* ws = as + A_CH_FLOATS;

        // register double-buffered fragment pipeline over 8 k-steps
        float4 a_f[2][4], b_f[2][4];
#pragma unroll
        for (int mt = 0; mt < 4; mt++)
            a_f[0][mt] = *(const float4*)(as + (((0 * 8 + m16b + mt) * 32) + lane) * 4);
#pragma unroll
        for (int ntp = 0; ntp < 4; ntp++)
            b_f[0][ntp] = *(const float4*)(ws + (((0 * 16 + nbpb + ntp) * 32) + lane) * 4);

#pragma unroll
        for (int ks = 0; ks < 8; ks++) {
            const int cur = ks & 1, nxt = cur ^ 1;
            if (ks < 7) {
#pragma unroll
                for (int mt = 0; mt < 4; mt++)
                    a_f[nxt][mt] = *(const float4*)(as + ((((ks + 1) * 8 + m16b + mt) * 32) + lane) * 4);
#pragma unroll
                for (int ntp = 0; ntp < 4; ntp++)
                    b_f[nxt][ntp] = *(const float4*)(ws + ((((ks + 1) * 16 + nbpb + ntp) * 32) + lane) * 4);
            }
#pragma unroll
            for (int ntp = 0; ntp < 4; ntp++) {
                uint32_t b0a = __float_as_uint(b_f[cur][ntp].x);
                uint32_t b1a = __float_as_uint(b_f[cur][ntp].y);
                uint32_t b0b = __float_as_uint(b_f[cur][ntp].z);
                uint32_t b1b = __float_as_uint(b_f[cur][ntp].w);
#pragma unroll
                for (int mt = 0; mt < 4; mt++) {
                    uint32_t af[4] = { __float_as_uint(a_f[cur][mt].x), __float_as_uint(a_f[cur][mt].y),
                                       __float_as_uint(a_f[cur][mt].z), __float_as_uint(a_f[cur][mt].w) };
                    mma_tf32(acc[mt][2 * ntp],     af, b0a, b1a);
                    mma_tf32(acc[mt][2 * ntp + 1], af, b0b, b1b);
                }
            }
        }
        __syncthreads();
    }

    // ---- epilogue: bias + gates + cell update + frag h image ----
    const int pg = tig & 1;
    float* hl = g_h[par ^ 1];
    float* hf = g_hFrag[par ^ 1] + ((size_t)mtile * 16 + utile) * A_CH_FLOATS;
#pragma unroll
    for (int mt = 0; mt < 4; mt++) {
        const int r1 = m0 + wm0 + mt * 16 + gid;
        const int m16 = m16b + mt;
#pragma unroll
        for (int nt = 0; nt < 8; nt++) {
            float c0 = acc[mt][nt][0], c1 = acc[mt][nt][1];
            float c2 = acc[mt][nt][2], c3 = acc[mt][nt][3];
            const int col  = wn0 + nt * 8 + 2 * tig;
            const int unit = u0 + (col >> 2);
            const float ba0 = pg ? __ldg(bias + 2 * U_SZ + unit) : __ldg(bias + unit);
            const float ba1 = pg ? __ldg(bias + 3 * U_SZ + unit) : __ldg(bias + U_SZ + unit);
            c0 += ba0; c1 += ba1; c2 += ba0; c3 += ba1;

            float s0 = __shfl_xor_sync(0xffffffffu, c0, 1);
            float s1 = __shfl_xor_sync(0xffffffffu, c1, 1);
            float s2 = __shfl_xor_sync(0xffffffffu, c2, 1);
            float s3 = __shfl_xor_sync(0xffffffffu, c3, 1);

            const int ul   = unit & 63;
            const int ks2  = ul >> 3, tig2 = ul & 3, khi2 = (ul >> 2) & 1;
            const int lane2 = gid * 4 + tig2;

            {   // row r1
                float gi = pg ? s0 : c0, gf = pg ? s1 : c1;
                float gg = pg ? c0 : s0, go = pg ? c1 : s1;
                int idx = r1 * U_SZ + unit;
                float cold = g_c[idx];
                float cn = sigm(gf) * cold + sigm(gi) * tanhf(gg);
                float hv = sigm(go) * tanhf(cn);
                if (!pg) {
                    g_c[idx] = cn; hl[idx] = hv;
                    hf[(((ks2 * 8 + m16) * 32) + lane2) * 4 + (khi2 * 2 + 0)] = to_tf32(hv);
                }
            }
            {   // row r1 + 8
                float gi = pg ? s2 : c2, gf = pg ? s3 : c3;
                float gg = pg ? c2 : s2, go = pg ? c3 : s3;
                int idx = (r1 + 8) * U_SZ + unit;
                float cold = g_c[idx];
                float cn = sigm(gf) * cold + sigm(gi) * tanhf(gg);
                float hv = sigm(go) * tanhf(cn);
                if (!pg) {
                    g_c[idx] = cn; hl[idx] = hv;
                    hf[(((ks2 * 8 + m16) * 32) + lane2) * 4 + (khi2 * 2 + 1)] = to_tf32(hv);
                }
            }
        }
    }
}

// ---------------- dense head ----------------
__global__ __launch_bounds__(256)
void dense_head_kernel(int par, const float* __restrict__ Wd, const float* __restrict__ bd,
                       const int* __restrict__ oidx, int n_idx,
                       float* __restrict__ out, int s, int S) {
    __shared__ float hs[8 * U_SZ];
    const int tid = threadIdx.x;
    const int r0 = blockIdx.x * 8;
    const float* h = g_h[par];
    for (int i = tid; i < 8 * U_SZ; i += 256)
        hs[i] = h[(size_t)(r0 + (i >> 10)) * U_SZ + (i & 1023)];
    __syncthreads();

    const int icol = tid & 63;
    const int rr = tid >> 6;
#pragma unroll
    for (int rp = 0; rp < 2; rp++) {
        const int r = rr + rp * 4;
        const float* hrow = hs + r * U_SZ;
        float a0 = 0.f, a1 = 0.f, a2 = 0.f, a3 = 0.f;
#pragma unroll 4
        for (int u = 0; u < U_SZ; u += 4) {
            a0 += hrow[u]     * __ldg(Wd + (size_t)u * I_SZ + icol);
            a1 += hrow[u + 1] * __ldg(Wd + (size_t)(u + 1) * I_SZ + icol);
            a2 += hrow[u + 2] * __ldg(Wd + (size_t)(u + 2) * I_SZ + icol);
            a3 += hrow[u + 3] * __ldg(Wd + (size_t)(u + 3) * I_SZ + icol);
        }
        float acc = __ldg(bd + icol) + (a0 + a1) + (a2 + a3);
        const int gb = r0 + r;
        int mtile = gb >> 7, m = gb & 127;
        g_pFrag[(size_t)mtile * A_CH_FLOATS + a_frag_idx(m, icol)] = to_tf32(acc);
        for (int j = 0; j < n_idx; j++)
            if (__ldg(oidx + j) == icol)
                out[(size_t)gb * S * n_idx + s * n_idx + j] = acc;
    }
}

// ---------------- launch ----------------
extern "C" void kernel_launch(void* const* d_in, const int* in_sizes, int n_in,
                              void* d_out, int out_size) {
    const float* inputs = (const float*)d_in[0];
    const float* Wk     = (const float*)d_in[1];
    const float* Wr     = (const float*)d_in[2];
    const float* bias   = (const float*)d_in[3];
    const float* Wd     = (const float*)d_in[4];
    const float* bd     = (const float*)d_in[5];
    const int*   oidx   = (const int*)d_in[6];
    float*       out    = (float*)d_out;

    const int T     = in_sizes[0] / (B_SZ * I_SZ);   // 256
    const int n_idx = in_sizes[6];                   // 2
    const int S     = out_size / (B_SZ * n_idx);     // 64

    cudaFuncSetAttribute(lstm_step_kernel,
                         cudaFuncAttributeMaxDynamicSharedMemorySize, SMEM_BYTES);

    init_state_kernel<<<(B_SZ * U_SZ + 255) / 256, 256>>>();
    prep_x_kernel<<<(B_SZ * T_SZ * I_SZ + 255) / 256, 256>>>(inputs);
    prep_w_kernel<<<(NCHK * 16 * W_CH_FLOATS + 255) / 256, 256>>>(Wk, Wr);

    int par = 0;
    for (int t = 0; t < T; t++) {
        lstm_step_kernel<<<128, 256, SMEM_BYTES>>>(t, par, 0, bias);
        par ^= 1;
    }
    dense_head_kernel<<<128, 256>>>(par, Wd, bd, oidx, n_idx, out, 0, S);
    for (int s = 1; s < S; s++) {
        lstm_step_kernel<<<128, 256, SMEM_BYTES>>>(0, par, 1, bias);
        par ^= 1;
        dense_head_kernel<<<128, 256>>>(par, Wd, bd, oidx, n_idx, out, s, S);
    }
}

// round 7
// speedup vs baseline: 1.8716x; 1.1571x over previous
#include <cuda_runtime.h>
#include <cstdint>

// Shapes (specialized)
#define B_SZ   1024
#define I_SZ   64
#define U_SZ   1024
#define T_SZ   256
#define KC     64          // K per chunk
#define NCHK   17          // (64+1024)/64
#define BM     128
#define BN     256         // 64 units x 4 gates (col = 4*u_local + gate)
#define UN     64
#define NTHR   512         // 16 warps: 4 in M x 4 in N, warp tile 32x64

// Fragment-major chunk images:
//  A chunk:  [ks(8)][m16(8)][lane(32)][q(4)]  = 8192 floats = 32KB
//  W chunk:  [ks(8)][nbp(16)][lane(32)][jp(4)] = 16384 floats = 64KB
#define A_CH_FLOATS 8192
#define W_CH_FLOATS 16384
#define STAGE_FLOATS (A_CH_FLOATS + W_CH_FLOATS)       // 24576 = 96KB
#define SMEM_BYTES (2 * STAGE_FLOATS * 4)              // 192KB

// ---------------- device state ----------------
__device__ float g_h[2][B_SZ * U_SZ];                   // linear h (dense head)
__device__ float g_c[B_SZ * U_SZ];
__device__ float g_hFrag[2][8 * 16 * A_CH_FLOATS];      // [par][mtile][ch-1][frag]
__device__ float g_xFrag[8 * 256 * A_CH_FLOATS];        // [mtile][t][frag]
__device__ float g_pFrag[8 * A_CH_FLOATS];              // [mtile][frag]
__device__ float g_WFrag[NCHK * 16 * W_CH_FLOATS];      // [kc][utile][frag]

// ---------------- helpers ----------------
__device__ __forceinline__ float to_tf32(float x) {
    uint32_t u; asm("cvt.rna.tf32.f32 %0, %1;" : "=r"(u) : "f"(x));
    return __uint_as_float(u);
}
__device__ __forceinline__ void mma_tf32(float (&d)[4], const uint32_t (&a)[4],
                                         uint32_t b0, uint32_t b1) {
    asm volatile(
        "mma.sync.aligned.m16n8k8.row.col.f32.tf32.tf32.f32 "
        "{%0,%1,%2,%3}, {%4,%5,%6,%7}, {%8,%9}, {%0,%1,%2,%3};\n"
        : "+f"(d[0]), "+f"(d[1]), "+f"(d[2]), "+f"(d[3])
        : "r"(a[0]), "r"(a[1]), "r"(a[2]), "r"(a[3]), "r"(b0), "r"(b1));
}
__device__ __forceinline__ void cp16(uint32_t dst, const void* src) {
    asm volatile("cp.async.cg.shared.global [%0], [%1], 16;\n" :: "r"(dst), "l"(src));
}
__device__ __forceinline__ float sigm(float x) { return 1.0f / (1.0f + expf(-x)); }

// frag index for an A-side element (m_local in [0,128), k in [0,64)) within a chunk
__device__ __forceinline__ int a_frag_idx(int m_local, int k) {
    int m16 = m_local >> 4, r16 = m_local & 15;
    int rhi = r16 >> 3, gid = r16 & 7;
    int ks = k >> 3, tig = k & 3, khi = (k >> 2) & 1;
    return (((ks * 8 + m16) * 32) + (gid * 4 + tig)) * 4 + (khi * 2 + rhi);
}

// ---------------- prep kernels (once per launch) ----------------
__global__ void init_state_kernel() {
    int i = blockIdx.x * blockDim.x + threadIdx.x;
    if (i < B_SZ * U_SZ) g_c[i] = 0.0f;
    if (i < 8 * 16 * A_CH_FLOATS) g_hFrag[0][i] = 0.0f;
}

__global__ void prep_x_kernel(const float* __restrict__ x) {
    int i = blockIdx.x * blockDim.x + threadIdx.x;   // over B*T*I
    if (i >= B_SZ * T_SZ * I_SZ) return;
    int col = i & 63, t = (i >> 6) & 255, row = i >> 14;
    int mtile = row >> 7, m = row & 127;
    g_xFrag[((size_t)mtile * 256 + t) * A_CH_FLOATS + a_frag_idx(m, col)] = to_tf32(x[i]);
}

__global__ void prep_w_kernel(const float* __restrict__ Wk, const float* __restrict__ Wr) {
    int i = blockIdx.x * blockDim.x + threadIdx.x;   // over NCHK*16*W_CH_FLOATS
    if (i >= NCHK * 16 * W_CH_FLOATS) return;
    int jp    = i & 3;            // j = jp>>1 (n-tile pair member), p = jp&1 (k half)
    int lane  = (i >> 2) & 31;
    int nbp   = (i >> 7) & 15;
    int ks    = (i >> 11) & 7;
    int utile = (i >> 14) & 15;
    int kc    = i >> 18;          // 16*W_CH_FLOATS = 2^18
    int gid = lane >> 2, tig = lane & 3;
    int n_local = (nbp * 2 + (jp >> 1)) * 8 + gid;    // 0..255, = 4*u_local + gate
    int ul = n_local >> 2, gate = n_local & 3;
    int colW = gate * U_SZ + utile * UN + ul;
    int kg = kc * KC + ks * 8 + tig + 4 * (jp & 1);
    float v = (kg < I_SZ) ? Wk[(size_t)kg * 4096 + colW]
                          : Wr[(size_t)(kg - I_SZ) * 4096 + colW];
    g_WFrag[i] = to_tf32(v);
}

// ---------------- LSTM step (512 threads, 16 warps) ----------------
__global__ __launch_bounds__(NTHR, 1)
void lstm_step_kernel(int t, int par, int use_pred, const float* __restrict__ bias) {
    extern __shared__ float sm[];
    uint32_t smb;
    asm("{ .reg .u64 t; cvta.to.shared.u64 t, %1; cvt.u32.u64 %0, t; }" : "=r"(smb) : "l"(sm));

    const int tid  = threadIdx.x;
    const int lane = tid & 31;
    const int wid  = tid >> 5;        // 0..15
    const int gid  = lane >> 2;
    const int tig  = lane & 3;

    const int utile = blockIdx.x & 15;
    const int mtile = blockIdx.x >> 4;
    const int u0 = utile * UN;
    const int m0 = mtile * BM;

    const int wmi = wid >> 2;         // 0..3 (M warp)
    const int wni = wid & 3;          // 0..3 (N warp)
    const int wm0 = wmi * 32;         // warp M offset
    const int wn0 = wni * 64;         // warp N offset
    const int m16b = wmi * 2;         // A frag m16 base (+mt, mt in 0..1)
    const int nbpb = wni * 4;         // W frag nbp base (+ntp)

    // issue cp.async for chunk ch into stage ch&1 (pure linear 16B copies)
    auto issue = [&](int ch) {
        uint32_t stg = smb + (uint32_t)(ch & 1) * (STAGE_FLOATS * 4u);
        const float4* a;
        if (ch == 0)
            a = use_pred ? (const float4*)(g_pFrag + (size_t)mtile * A_CH_FLOATS)
                         : (const float4*)(g_xFrag + ((size_t)mtile * 256 + t) * A_CH_FLOATS);
        else
            a = (const float4*)(g_hFrag[par] + ((size_t)mtile * 16 + (ch - 1)) * A_CH_FLOATS);
#pragma unroll
        for (int j = 0; j < 4; j++)
            cp16(stg + (uint32_t)(tid + j * NTHR) * 16u, a + tid + j * NTHR);
        const float4* b = (const float4*)(g_WFrag + ((size_t)ch * 16 + utile) * W_CH_FLOATS);
#pragma unroll
        for (int j = 0; j < 8; j++)
            cp16(stg + A_CH_FLOATS * 4u + (uint32_t)(tid + j * NTHR) * 16u, b + tid + j * NTHR);
        asm volatile("cp.async.commit_group;\n");
    };

    float acc[2][8][4];
#pragma unroll
    for (int mt = 0; mt < 2; mt++)
#pragma unroll
        for (int nt = 0; nt < 8; nt++)
#pragma unroll
            for (int q = 0; q < 4; q++) acc[mt][nt][q] = 0.0f;

    issue(0);

    for (int ch = 0; ch < NCHK; ch++) {
        if (ch + 1 < NCHK) {
            issue(ch + 1);
            asm volatile("cp.async.wait_group 1;\n" ::: "memory");
        } else {
            asm volatile("cp.async.wait_group 0;\n" ::: "memory");
        }
        __syncthreads();

        const float* as = sm + (ch & 1) * STAGE_FLOATS;
        const float* ws = as + A_CH_FLOATS;

#pragma unroll
        for (int ks = 0; ks < 8; ks++) {
            // single-buffered frags; 4 warps/SMSP cover the LDS latency
            float4 a_f[2], b_f[4];
#pragma unroll
            for (int mt = 0; mt < 2; mt++)
                a_f[mt] = *(const float4*)(as + (((ks * 8 + m16b + mt) * 32) + lane) * 4);
#pragma unroll
            for (int ntp = 0; ntp < 4; ntp++)
                b_f[ntp] = *(const float4*)(ws + (((ks * 16 + nbpb + ntp) * 32) + lane) * 4);

#pragma unroll
            for (int ntp = 0; ntp < 4; ntp++) {
                uint32_t b0a = __float_as_uint(b_f[ntp].x);
                uint32_t b1a = __float_as_uint(b_f[ntp].y);
                uint32_t b0b = __float_as_uint(b_f[ntp].z);
                uint32_t b1b = __float_as_uint(b_f[ntp].w);
#pragma unroll
                for (int mt = 0; mt < 2; mt++) {
                    uint32_t af[4] = { __float_as_uint(a_f[mt].x), __float_as_uint(a_f[mt].y),
                                       __float_as_uint(a_f[mt].z), __float_as_uint(a_f[mt].w) };
                    mma_tf32(acc[mt][2 * ntp],     af, b0a, b1a);
                    mma_tf32(acc[mt][2 * ntp + 1], af, b0b, b1b);
                }
            }
        }
        __syncthreads();
    }

    // ---- epilogue: bias + gates + cell update + frag h image ----
    const int pg = tig & 1;
    float* hl = g_h[par ^ 1];
    float* hf = g_hFrag[par ^ 1] + ((size_t)mtile * 16 + utile) * A_CH_FLOATS;
#pragma unroll
    for (int mt = 0; mt < 2; mt++) {
        const int r1 = m0 + wm0 + mt * 16 + gid;
        const int m16 = m16b + mt;
#pragma unroll
        for (int nt = 0; nt < 8; nt++) {
            float c0 = acc[mt][nt][0], c1 = acc[mt][nt][1];
            float c2 = acc[mt][nt][2], c3 = acc[mt][nt][3];
            const int col  = wn0 + nt * 8 + 2 * tig;
            const int unit = u0 + (col >> 2);
            const float ba0 = pg ? __ldg(bias + 2 * U_SZ + unit) : __ldg(bias + unit);
            const float ba1 = pg ? __ldg(bias + 3 * U_SZ + unit) : __ldg(bias + U_SZ + unit);
            c0 += ba0; c1 += ba1; c2 += ba0; c3 += ba1;

            float s0 = __shfl_xor_sync(0xffffffffu, c0, 1);
            float s1 = __shfl_xor_sync(0xffffffffu, c1, 1);
            float s2 = __shfl_xor_sync(0xffffffffu, c2, 1);
            float s3 = __shfl_xor_sync(0xffffffffu, c3, 1);

            const int ul   = unit & 63;
            const int ks2  = ul >> 3, tig2 = ul & 3, khi2 = (ul >> 2) & 1;
            const int lane2 = gid * 4 + tig2;

            {   // row r1
                float gi = pg ? s0 : c0, gf = pg ? s1 : c1;
                float gg = pg ? c0 : s0, go = pg ? c1 : s1;
                int idx = r1 * U_SZ + unit;
                float cold = g_c[idx];
                float cn = sigm(gf) * cold + sigm(gi) * tanhf(gg);
                float hv = sigm(go) * tanhf(cn);
                if (!pg) {
                    g_c[idx] = cn; hl[idx] = hv;
                    hf[(((ks2 * 8 + m16) * 32) + lane2) * 4 + (khi2 * 2 + 0)] = to_tf32(hv);
                }
            }
            {   // row r1 + 8
                float gi = pg ? s2 : c2, gf = pg ? s3 : c3;
                float gg = pg ? c2 : s2, go = pg ? c3 : s3;
                int idx = (r1 + 8) * U_SZ + unit;
                float cold = g_c[idx];
                float cn = sigm(gf) * cold + sigm(gi) * tanhf(gg);
                float hv = sigm(go) * tanhf(cn);
                if (!pg) {
                    g_c[idx] = cn; hl[idx] = hv;
                    hf[(((ks2 * 8 + m16) * 32) + lane2) * 4 + (khi2 * 2 + 1)] = to_tf32(hv);
                }
            }
        }
    }
}

// ---------------- dense head ----------------
__global__ __launch_bounds__(256)
void dense_head_kernel(int par, const float* __restrict__ Wd, const float* __restrict__ bd,
                       const int* __restrict__ oidx, int n_idx,
                       float* __restrict__ out, int s, int S) {
    __shared__ float hs[8 * U_SZ];
    const int tid = threadIdx.x;
    const int r0 = blockIdx.x * 8;
    const float* h = g_h[par];
    for (int i = tid; i < 8 * U_SZ; i += 256)
        hs[i] = h[(size_t)(r0 + (i >> 10)) * U_SZ + (i & 1023)];
    __syncthreads();

    const int icol = tid & 63;
    const int rr = tid >> 6;
#pragma unroll
    for (int rp = 0; rp < 2; rp++) {
        const int r = rr + rp * 4;
        const float* hrow = hs + r * U_SZ;
        float a0 = 0.f, a1 = 0.f, a2 = 0.f, a3 = 0.f;
#pragma unroll 4
        for (int u = 0; u < U_SZ; u += 4) {
            a0 += hrow[u]     * __ldg(Wd + (size_t)u * I_SZ + icol);
            a1 += hrow[u + 1] * __ldg(Wd + (size_t)(u + 1) * I_SZ + icol);
            a2 += hrow[u + 2] * __ldg(Wd + (size_t)(u + 2) * I_SZ + icol);
            a3 += hrow[u + 3] * __ldg(Wd + (size_t)(u + 3) * I_SZ + icol);
        }
        float acc = __ldg(bd + icol) + (a0 + a1) + (a2 + a3);
        const int gb = r0 + r;
        int mtile = gb >> 7, m = gb & 127;
        g_pFrag[(size_t)mtile * A_CH_FLOATS + a_frag_idx(m, icol)] = to_tf32(acc);
        for (int j = 0; j < n_idx; j++)
            if (__ldg(oidx + j) == icol)
                out[(size_t)gb * S * n_idx + s * n_idx + j] = acc;
    }
}

// ---------------- launch ----------------
extern "C" void kernel_launch(void* const* d_in, const int* in_sizes, int n_in,
                              void* d_out, int out_size) {
    const float* inputs = (const float*)d_in[0];
    const float* Wk     = (const float*)d_in[1];
    const float* Wr     = (const float*)d_in[2];
    const float* bias   = (const float*)d_in[3];
    const float* Wd     = (const float*)d_in[4];
    const float* bd     = (const float*)d_in[5];
    const int*   oidx   = (const int*)d_in[6];
    float*       out    = (float*)d_out;

    const int T     = in_sizes[0] / (B_SZ * I_SZ);   // 256
    const int n_idx = in_sizes[6];                   // 2
    const int S     = out_size / (B_SZ * n_idx);     // 64

    cudaFuncSetAttribute(lstm_step_kernel,
                         cudaFuncAttributeMaxDynamicSharedMemorySize, SMEM_BYTES);

    init_state_kernel<<<(B_SZ * U_SZ + 255) / 256, 256>>>();
    prep_x_kernel<<<(B_SZ * T_SZ * I_SZ + 255) / 256, 256>>>(inputs);
    prep_w_kernel<<<(NCHK * 16 * W_CH_FLOATS + 255) / 256, 256>>>(Wk, Wr);

    int par = 0;
    for (int t = 0; t < T; t++) {
        lstm_step_kernel<<<128, NTHR, SMEM_BYTES>>>(t, par, 0, bias);
        par ^= 1;
    }
    dense_head_kernel<<<128, 256>>>(par, Wd, bd, oidx, n_idx, out, 0, S);
    for (int s = 1; s < S; s++) {
        lstm_step_kernel<<<128, NTHR, SMEM_BYTES>>>(0, par, 1, bias);
        par ^= 1;
        dense_head_kernel<<<128, 256>>>(par, Wd, bd, oidx, n_idx, out, s, S);
    }
}

// round 10
// speedup vs baseline: 2.6482x; 1.4149x over previous
#include <cuda_runtime.h>
#include <cuda_fp16.h>
#include <cstdint>

// Shapes (specialized)
#define B_SZ   1024
#define I_SZ   64
#define U_SZ   1024
#define T_SZ   256
#define KC     64          // K per chunk
#define NCHK   17          // (64+1024)/64
#define BM     128
#define BN     256         // 64 units x 4 gates (col = 4*u_local + gate)
#define UN     64
#define NTHR   512         // 16 warps: 4 in M x 4 in N, warp tile 32x64

// fp16 fragment-major chunk images (m16n8k16):
//  A chunk: [ks(4)][m16(8)][lane(32)][q(4)] u32 (each u32 = 2 halfs) = 4096 u32 = 16KB
//  W chunk: [ks(4)][nbp(16)][lane(32)][jp(4)] u32                    = 8192 u32 = 32KB
#define A_CH_U32  4096
#define W_CH_U32  8192
#define A_CH_HALF (A_CH_U32 * 2)
#define W_CH_HALF (W_CH_U32 * 2)
#define STAGE_U32 (A_CH_U32 + W_CH_U32)        // 12288 u32 = 48KB
#define NSTAGE    4
#define SMEM_BYTES (NSTAGE * STAGE_U32 * 4)    // 192KB

// ---------------- device state ----------------
__device__ float  g_h[2][B_SZ * U_SZ];                  // linear h (dense head)
__device__ float  g_c[B_SZ * U_SZ];
__device__ __half g_hFrag[2][8 * 16 * A_CH_HALF];       // [par][mtile][ch-1][frag]
__device__ __half g_xFrag[8 * 256 * A_CH_HALF];         // [mtile][t][frag]
__device__ __half g_pFrag[8 * A_CH_HALF];               // [mtile][frag]
__device__ __half g_WFrag[NCHK * 16 * W_CH_HALF];       // [kc][utile][frag]

// ---------------- helpers ----------------
__device__ __forceinline__ void mma_f16(float (&d)[4], const uint32_t (&a)[4],
                                        uint32_t b0, uint32_t b1) {
    asm volatile(
        "mma.sync.aligned.m16n8k16.row.col.f32.f16.f16.f32 "
        "{%0,%1,%2,%3}, {%4,%5,%6,%7}, {%8,%9}, {%0,%1,%2,%3};\n"
        : "+f"(d[0]), "+f"(d[1]), "+f"(d[2]), "+f"(d[3])
        : "r"(a[0]), "r"(a[1]), "r"(a[2]), "r"(a[3]), "r"(b0), "r"(b1));
}
__device__ __forceinline__ void cp16(uint32_t dst, const void* src) {
    asm volatile("cp.async.cg.shared.global [%0], [%1], 16;\n" :: "r"(dst), "l"(src));
}
__device__ __forceinline__ void cp_commit() {
    asm volatile("cp.async.commit_group;\n");
}
__device__ __forceinline__ float sigm(float x) { return 1.0f / (1.0f + expf(-x)); }

// half index of A-side element (m in [0,128), k in [0,64)) within a chunk image
// m16n8k16 A frag: thread(g,t): a0=(g,2t),(g,2t+1) a1=(g+8,..) a2=(g,2t+8).. a3=(g+8,2t+8)..
__device__ __forceinline__ int a_frag_hidx(int m, int k) {
    int ks = k >> 4, kin = k & 15;
    int khi = kin >> 3, tigk = (kin & 7) >> 1, hsel = kin & 1;
    int m16 = m >> 4, r16 = m & 15, gid = r16 & 7, rhi = r16 >> 3;
    int lane = gid * 4 + tigk;
    int q = khi * 2 + rhi;
    return ((((ks * 8 + m16) * 32) + lane) * 4 + q) * 2 + hsel;
}

// plain function (no lambda): issue one chunk's cp.async group
__device__ __forceinline__ void issue_chunk(int ch, uint32_t smb, int tid,
                                            int mtile, int utile,
                                            int t, int par, int use_pred) {
    uint32_t stg = smb + (uint32_t)(ch & 3) * (STAGE_U32 * 4u);
    const uint4* a;
    if (ch == 0) {
        a = use_pred ? (const uint4*)(g_pFrag + (size_t)mtile * A_CH_HALF)
                     : (const uint4*)(g_xFrag + ((size_t)mtile * 256 + t) * A_CH_HALF);
    } else {
        a = (const uint4*)(g_hFrag[par] + ((size_t)mtile * 16 + (ch - 1)) * A_CH_HALF);
    }
    cp16(stg + (uint32_t)tid * 16u,                 a + tid);
    cp16(stg + (uint32_t)(tid + NTHR) * 16u,        a + tid + NTHR);
    const uint4* b = (const uint4*)(g_WFrag + ((size_t)ch * 16 + utile) * W_CH_HALF);
    uint32_t wbase = stg + A_CH_U32 * 4u;
    cp16(wbase + (uint32_t)tid * 16u,               b + tid);
    cp16(wbase + (uint32_t)(tid + NTHR) * 16u,      b + tid + NTHR);
    cp16(wbase + (uint32_t)(tid + 2 * NTHR) * 16u,  b + tid + 2 * NTHR);
    cp16(wbase + (uint32_t)(tid + 3 * NTHR) * 16u,  b + tid + 3 * NTHR);
    cp_commit();
}

// ---------------- prep kernels (once per launch) ----------------
__global__ void init_state_kernel() {
    int i = blockIdx.x * blockDim.x + threadIdx.x;
    if (i < B_SZ * U_SZ) g_c[i] = 0.0f;
    if (i < 8 * 16 * A_CH_HALF) g_hFrag[0][i] = __float2half(0.0f);
}

__global__ void prep_x_kernel(const float* __restrict__ x) {
    int i = blockIdx.x * blockDim.x + threadIdx.x;   // over B*T*I
    if (i >= B_SZ * T_SZ * I_SZ) return;
    int col = i & 63, t = (i >> 6) & 255, row = i >> 14;
    int mtile = row >> 7, m = row & 127;
    g_xFrag[((size_t)mtile * 256 + t) * A_CH_HALF + a_frag_hidx(m, col)] = __float2half_rn(x[i]);
}

// W frag: B tile col-major 16x8: thread(g,t): b0=(2t,g),(2t+1,g) b1=(2t+8,g),(2t+9,g)
__global__ void prep_w_kernel(const float* __restrict__ Wk, const float* __restrict__ Wr) {
    int i = blockIdx.x * blockDim.x + threadIdx.x;   // over NCHK*16*W_CH_HALF
    if (i >= NCHK * 16 * W_CH_HALF) return;
    int hsel  = i & 1;
    int jp    = (i >> 1) & 3;          // j = jp>>1 (n8 within pair), bhi = jp&1
    int lane  = (i >> 3) & 31;
    int nbp   = (i >> 8) & 15;
    int ks    = (i >> 12) & 3;
    int utile = (i >> 14) & 15;
    int kc    = i >> 18;               // 16*W_CH_HALF = 2^18
    int gid = lane >> 2, tigk = lane & 3;
    int n8 = nbp * 2 + (jp >> 1);
    int bhi = jp & 1;
    int n_local = n8 * 8 + gid;                        // 0..255 = 4*u_local + gate
    int ul = n_local >> 2, gate = n_local & 3;
    int colW = gate * U_SZ + utile * UN + ul;
    int kg = kc * KC + ks * 16 + bhi * 8 + tigk * 2 + hsel;
    float v = (kg < I_SZ) ? Wk[(size_t)kg * 4096 + colW]
                          : Wr[(size_t)(kg - I_SZ) * 4096 + colW];
    g_WFrag[i] = __float2half_rn(v);
}

// ---------------- LSTM step (512 threads, fp16 k16 MMA, 4-stage ring) ----------------
__global__ __launch_bounds__(NTHR, 1)
void lstm_step_kernel(int t, int par, int use_pred, const float* __restrict__ bias) {
    extern __shared__ uint32_t smu[];
    uint32_t smb;
    asm("{ .reg .u64 t; cvta.to.shared.u64 t, %1; cvt.u32.u64 %0, t; }" : "=r"(smb) : "l"(smu));

    const int tid  = threadIdx.x;
    const int lane = tid & 31;
    const int wid  = tid >> 5;        // 0..15
    const int gid  = lane >> 2;
    const int tig  = lane & 3;

    const int utile = blockIdx.x & 15;
    const int mtile = blockIdx.x >> 4;
    const int u0 = utile * UN;
    const int m0 = mtile * BM;

    const int wmi = wid >> 2;         // M warp 0..3
    const int wni = wid & 3;          // N warp 0..3
    const int wm0 = wmi * 32;
    const int wn0 = wni * 64;
    const int m16b = wmi * 2;         // A m16 base (+mt in 0..1)
    const int nbpb = wni * 4;         // W nbp base (+ntp in 0..3)

    float acc[2][8][4];
#pragma unroll
    for (int mt = 0; mt < 2; mt++)
#pragma unroll
        for (int nt = 0; nt < 8; nt++)
#pragma unroll
            for (int q = 0; q < 4; q++) acc[mt][nt][q] = 0.0f;

    // prologue: fill 3 stages
    issue_chunk(0, smb, tid, mtile, utile, t, par, use_pred);
    issue_chunk(1, smb, tid, mtile, utile, t, par, use_pred);
    issue_chunk(2, smb, tid, mtile, utile, t, par, use_pred);

    for (int ch = 0; ch < NCHK; ch++) {
        if (ch + 3 < NCHK) {
            issue_chunk(ch + 3, smb, tid, mtile, utile, t, par, use_pred);
            asm volatile("cp.async.wait_group 3;\n" ::: "memory");
        } else if (ch + 3 == NCHK) {
            asm volatile("cp.async.wait_group 2;\n" ::: "memory");
        } else if (ch + 3 == NCHK + 1) {
            asm volatile("cp.async.wait_group 1;\n" ::: "memory");
        } else {
            asm volatile("cp.async.wait_group 0;\n" ::: "memory");
        }
        __syncthreads();

        const uint32_t* as = smu + (ch & 3) * STAGE_U32;
        const uint32_t* ws = as + A_CH_U32;

#pragma unroll
        for (int ks = 0; ks < 4; ks++) {
            uint4 a_f[2], b_f[4];
#pragma unroll
            for (int mt = 0; mt < 2; mt++)
                a_f[mt] = *(const uint4*)(as + (((ks * 8 + m16b + mt) * 32) + lane) * 4);
#pragma unroll
            for (int ntp = 0; ntp < 4; ntp++)
                b_f[ntp] = *(const uint4*)(ws + (((ks * 16 + nbpb + ntp) * 32) + lane) * 4);

#pragma unroll
            for (int ntp = 0; ntp < 4; ntp++) {
#pragma unroll
                for (int mt = 0; mt < 2; mt++) {
                    uint32_t af[4] = { a_f[mt].x, a_f[mt].y, a_f[mt].z, a_f[mt].w };
                    mma_f16(acc[mt][2 * ntp],     af, b_f[ntp].x, b_f[ntp].y);
                    mma_f16(acc[mt][2 * ntp + 1], af, b_f[ntp].z, b_f[ntp].w);
                }
            }
        }
        __syncthreads();
    }

    // ---- epilogue: bias + gates + cell update + fp16 frag h image ----
    const int pg = tig & 1;
    float*  hl = g_h[par ^ 1];
    __half* hf = g_hFrag[par ^ 1] + ((size_t)mtile * 16 + utile) * A_CH_HALF;
#pragma unroll
    for (int mt = 0; mt < 2; mt++) {
        const int r1 = m0 + wm0 + mt * 16 + gid;
        const int m16 = m16b + mt;
#pragma unroll
        for (int nt = 0; nt < 8; nt++) {
            float c0 = acc[mt][nt][0], c1 = acc[mt][nt][1];
            float c2 = acc[mt][nt][2], c3 = acc[mt][nt][3];
            const int col  = wn0 + nt * 8 + 2 * tig;
            const int unit = u0 + (col >> 2);
            const float ba0 = pg ? __ldg(bias + 2 * U_SZ + unit) : __ldg(bias + unit);
            const float ba1 = pg ? __ldg(bias + 3 * U_SZ + unit) : __ldg(bias + U_SZ + unit);
            c0 += ba0; c1 += ba1; c2 += ba0; c3 += ba1;

            float s0 = __shfl_xor_sync(0xffffffffu, c0, 1);
            float s1 = __shfl_xor_sync(0xffffffffu, c1, 1);
            float s2 = __shfl_xor_sync(0xffffffffu, c2, 1);
            float s3 = __shfl_xor_sync(0xffffffffu, c3, 1);

            // h frag slot for (row, unit): chunk = utile, klocal = unit & 63
            const int ul2  = unit & 63;
            const int ks2  = ul2 >> 4, kin = ul2 & 15;
            const int khi2 = kin >> 3, tig2 = (kin & 7) >> 1, hsel = kin & 1;
            const int lane2 = gid * 4 + tig2;

            {   // row r1 (rhi = 0)
                float gi = pg ? s0 : c0, gf = pg ? s1 : c1;
                float gg = pg ? c0 : s0, go = pg ? c1 : s1;
                int idx = r1 * U_SZ + unit;
                float cold = g_c[idx];
                float cn = sigm(gf) * cold + sigm(gi) * tanhf(gg);
                float hv = sigm(go) * tanhf(cn);
                if (!pg) {
                    g_c[idx] = cn; hl[idx] = hv;
                    int q = khi2 * 2 + 0;
                    hf[((((ks2 * 8 + m16) * 32) + lane2) * 4 + q) * 2 + hsel] = __float2half_rn(hv);
                }
            }
            {   // row r1 + 8 (rhi = 1)
                float gi = pg ? s2 : c2, gf = pg ? s3 : c3;
                float gg = pg ? c2 : s2, go = pg ? c3 : s3;
                int idx = (r1 + 8) * U_SZ + unit;
                float cold = g_c[idx];
                float cn = sigm(gf) * cold + sigm(gi) * tanhf(gg);
                float hv = sigm(go) * tanhf(cn);
                if (!pg) {
                    g_c[idx] = cn; hl[idx] = hv;
                    int q = khi2 * 2 + 1;
                    hf[((((ks2 * 8 + m16) * 32) + lane2) * 4 + q) * 2 + hsel] = __float2half_rn(hv);
                }
            }
        }
    }
}

// ---------------- dense head ----------------
__global__ __launch_bounds__(256)
void dense_head_kernel(int par, const float* __restrict__ Wd, const float* __restrict__ bd,
                       const int* __restrict__ oidx, int n_idx,
                       float* __restrict__ out, int s, int S) {
    __shared__ float hs[8 * U_SZ];
    const int tid = threadIdx.x;
    const int r0 = blockIdx.x * 8;
    const float* h = g_h[par];
    for (int i = tid; i < 8 * U_SZ; i += 256)
        hs[i] = h[(size_t)(r0 + (i >> 10)) * U_SZ + (i & 1023)];
    __syncthreads();

    const int icol = tid & 63;
    const int rr = tid >> 6;
#pragma unroll
    for (int rp = 0; rp < 2; rp++) {
        const int r = rr + rp * 4;
        const float* hrow = hs + r * U_SZ;
        float a0 = 0.f, a1 = 0.f, a2 = 0.f, a3 = 0.f;
#pragma unroll 4
        for (int u = 0; u < U_SZ; u += 4) {
            a0 += hrow[u]     * __ldg(Wd + (size_t)u * I_SZ + icol);
            a1 += hrow[u + 1] * __ldg(Wd + (size_t)(u + 1) * I_SZ + icol);
            a2 += hrow[u + 2] * __ldg(Wd + (size_t)(u + 2) * I_SZ + icol);
            a3 += hrow[u + 3] * __ldg(Wd + (size_t)(u + 3) * I_SZ + icol);
        }
        float acc = __ldg(bd + icol) + (a0 + a1) + (a2 + a3);
        const int gb = r0 + r;
        int mtile = gb >> 7, m = gb & 127;
        g_pFrag[(size_t)mtile * A_CH_HALF + a_frag_hidx(m, icol)] = __float2half_rn(acc);
        for (int j = 0; j < n_idx; j++)
            if (__ldg(oidx + j) == icol)
                out[(size_t)gb * S * n_idx + s * n_idx + j] = acc;
    }
}

// ---------------- launch ----------------
extern "C" void kernel_launch(void* const* d_in, const int* in_sizes, int n_in,
                              void* d_out, int out_size) {
    const float* inputs = (const float*)d_in[0];
    const float* Wk     = (const float*)d_in[1];
    const float* Wr     = (const float*)d_in[2];
    const float* bias   = (const float*)d_in[3];
    const float* Wd     = (const float*)d_in[4];
    const float* bd     = (const float*)d_in[5];
    const int*   oidx   = (const int*)d_in[6];
    float*       out    = (float*)d_out;

    const int T     = in_sizes[0] / (B_SZ * I_SZ);   // 256
    const int n_idx = in_sizes[6];                   // 2
    const int S     = out_size / (B_SZ * n_idx);     // 64

    cudaFuncSetAttribute(lstm_step_kernel,
                         cudaFuncAttributeMaxDynamicSharedMemorySize, SMEM_BYTES);

    init_state_kernel<<<(B_SZ * U_SZ + 255) / 256, 256>>>();
    prep_x_kernel<<<(B_SZ * T_SZ * I_SZ + 255) / 256, 256>>>(inputs);
    prep_w_kernel<<<(NCHK * 16 * W_CH_HALF + 255) / 256, 256>>>(Wk, Wr);

    int par = 0;
    for (int t = 0; t < T; t++) {
        lstm_step_kernel<<<128, NTHR, SMEM_BYTES>>>(t, par, 0, bias);
        par ^= 1;
    }
    dense_head_kernel<<<128, 256>>>(par, Wd, bd, oidx, n_idx, out, 0, S);
    for (int s = 1; s < S; s++) {
        lstm_step_kernel<<<128, NTHR, SMEM_BYTES>>>(0, par, 1, bias);
        par ^= 1;
        dense_head_kernel<<<128, 256>>>(par, Wd, bd, oidx, n_idx, out, s, S);
    }
}